// round 1
// baseline (speedup 1.0000x reference)
#include <cuda_runtime.h>
#include <math.h>

#define NN 20000
#define NE 320000
#define DH 128
#define DIN 64
#define NT 20
#define LNEPS 1e-5f

// ---------------- scratch (device globals: no allocation allowed) ----------
__device__ float g_dt;
__device__ float g_epi;

__device__ float d_g   [NN * DH];
__device__ float d_bufA[NN * DH];
__device__ float d_bufB[NN * DH];
__device__ float d_y   [NN * DH];
__device__ float d_k   [NN * DH];
__device__ float d_acc [NN * DH];
__device__ float d_h   [NN * DH];

__device__ float d_dis[NN];
__device__ int   d_counts[NN];
__device__ int   d_off[NN + 1];
__device__ int   d_cursor[NN];
__device__ int   d_csr_src[NE];

// ---------------- graph preprocessing --------------------------------------
__global__ void k_zero_counts() {
    int i = blockIdx.x * blockDim.x + threadIdx.x;
    if (i < NN) d_counts[i] = 0;
}

__global__ void k_count(const int* __restrict__ ei) {
    int e = blockIdx.x * blockDim.x + threadIdx.x;
    if (e < NE) atomicAdd(&d_counts[ei[NE + e]], 1);
}

// single-block exclusive scan of counts -> off, cursor
__global__ void k_scan() {
    __shared__ int sm[1024];
    int t = threadIdx.x;
    const int CH = (NN + 1023) / 1024;  // 20
    int beg = t * CH;
    int end = min(NN, beg + CH);
    int s = 0;
    for (int i = beg; i < end; i++) s += d_counts[i];
    sm[t] = s;
    __syncthreads();
    for (int o = 1; o < 1024; o <<= 1) {
        int v = (t >= o) ? sm[t - o] : 0;
        __syncthreads();
        sm[t] += v;
        __syncthreads();
    }
    int run = sm[t] - s;  // exclusive prefix
    for (int i = beg; i < end; i++) {
        d_off[i] = run;
        d_cursor[i] = run;
        run += d_counts[i];
    }
    if (t == 1023) d_off[NN] = sm[1023];
}

__global__ void k_dis() {
    int i = blockIdx.x * blockDim.x + threadIdx.x;
    if (i < NN) d_dis[i] = (d_counts[i] > 0) ? rsqrtf((float)d_counts[i]) : 0.f;
}

__global__ void k_fill(const int* __restrict__ ei) {
    int e = blockIdx.x * blockDim.x + threadIdx.x;
    if (e < NE) {
        int c = ei[NE + e];
        int p = atomicAdd(&d_cursor[c], 1);
        d_csr_src[p] = ei[e];
    }
}

// ---------------- scalars --------------------------------------------------
__global__ void k_dt(const float* __restrict__ log_depth) {
    float d = expf(log_depth[0]);
    d = fminf(fmaxf(d, 0.1f), 3.0f);
    g_dt = d / (float)(NT - 1);
}

__global__ void k_epi(const float* __restrict__ meth, const float* __restrict__ hist) {
    __shared__ float sm[4];
    int t = threadIdx.x;  // 128 threads
    float v = 1.f / (1.f + expf(-meth[t]));
    for (int o = 16; o > 0; o >>= 1) v += __shfl_xor_sync(0xffffffff, v, o);
    if ((t & 31) == 0) sm[t >> 5] = v;
    __syncthreads();
    if (t == 0) {
        float tot = sm[0] + sm[1] + sm[2] + sm[3];
        float ms = tot / 128.f;
        float h0 = 1.f / (1.f + expf(-hist[0]));
        float h1 = 1.f / (1.f + expf(-hist[1]));
        float h2 = 1.f / (1.f + expf(-hist[2]));
        float h3 = 1.f / (1.f + expf(-hist[3]));
        float act = 0.5f * (h0 + h2);
        float rep = 0.5f * (h1 + h3);
        float acc = fminf(fmaxf(act - rep + 0.5f, 0.f), 1.f);
        g_epi = acc * (1.f - ms);
    }
}

// ---------------- GEMM: C[M x 128] = A[M x K] @ W[K x 128] -----------------
// EPI 0: C = acc + bias[col]         (pre-LN projections)
// EPI 1: C = acc * dis[row]          (GCN message pre-scale)
template <int K, int EPI>
__global__ void k_gemm(const float* __restrict__ A, const float* __restrict__ W,
                       const float* __restrict__ bias, float* __restrict__ C, int M) {
    __shared__ float sA[16][65];
    __shared__ float sW[16][128];
    int tid = threadIdx.x;           // 256
    int tx = tid & 31, ty = tid >> 5;
    int r0 = blockIdx.x * 64;
    float acc[8][4];
#pragma unroll
    for (int i = 0; i < 8; i++)
#pragma unroll
        for (int j = 0; j < 4; j++) acc[i][j] = 0.f;

    for (int k0 = 0; k0 < K; k0 += 16) {
#pragma unroll
        for (int it = 0; it < 4; it++) {
            int idx = tid + it * 256;
            int r = idx >> 4, kk = idx & 15;
            int gr = r0 + r;
            sA[kk][r] = (gr < M) ? A[gr * K + k0 + kk] : 0.f;
        }
#pragma unroll
        for (int it = 0; it < 8; it++) {
            int idx = tid + it * 256;
            int kr = idx >> 7, c = idx & 127;
            sW[kr][c] = W[(k0 + kr) * DH + c];
        }
        __syncthreads();
#pragma unroll
        for (int kk = 0; kk < 16; kk++) {
            float4 w = *(const float4*)&sW[kk][tx * 4];
            float a[8];
#pragma unroll
            for (int i = 0; i < 8; i++) a[i] = sA[kk][ty * 8 + i];
#pragma unroll
            for (int i = 0; i < 8; i++) {
                acc[i][0] += a[i] * w.x;
                acc[i][1] += a[i] * w.y;
                acc[i][2] += a[i] * w.z;
                acc[i][3] += a[i] * w.w;
            }
        }
        __syncthreads();
    }
#pragma unroll
    for (int i = 0; i < 8; i++) {
        int r = r0 + ty * 8 + i;
        if (r < M) {
            float sc = (EPI == 1) ? d_dis[r] : 0.f;
#pragma unroll
            for (int j = 0; j < 4; j++) {
                int c = tx * 4 + j;
                float v = acc[i][j];
                if (EPI == 0) v += bias[c];
                else          v *= sc;
                C[r * DH + c] = v;
            }
        }
    }
}

// ---------------- gate: in-place hc = g*hn + (1-g)*hc ----------------------
__global__ void k_gate(float* hc, const float* __restrict__ hn,
                       const float* __restrict__ GW, const float* __restrict__ gb, int M) {
    __shared__ float sA[16][65];
    __shared__ float sW[16][128];
    int tid = threadIdx.x;
    int tx = tid & 31, ty = tid >> 5;
    int r0 = blockIdx.x * 64;
    float acc[8][4];
#pragma unroll
    for (int i = 0; i < 8; i++)
#pragma unroll
        for (int j = 0; j < 4; j++) acc[i][j] = 0.f;

    for (int k0 = 0; k0 < 2 * DH; k0 += 16) {
#pragma unroll
        for (int it = 0; it < 4; it++) {
            int idx = tid + it * 256;
            int r = idx >> 4, kk = idx & 15;
            int gr = r0 + r;
            int kg = k0 + kk;
            float v = 0.f;
            if (gr < M) v = (kg < DH) ? hc[gr * DH + kg] : hn[gr * DH + kg - DH];
            sA[kk][r] = v;
        }
#pragma unroll
        for (int it = 0; it < 8; it++) {
            int idx = tid + it * 256;
            int kr = idx >> 7, c = idx & 127;
            sW[kr][c] = GW[(k0 + kr) * DH + c];
        }
        __syncthreads();
#pragma unroll
        for (int kk = 0; kk < 16; kk++) {
            float4 w = *(const float4*)&sW[kk][tx * 4];
            float a[8];
#pragma unroll
            for (int i = 0; i < 8; i++) a[i] = sA[kk][ty * 8 + i];
#pragma unroll
            for (int i = 0; i < 8; i++) {
                acc[i][0] += a[i] * w.x;
                acc[i][1] += a[i] * w.y;
                acc[i][2] += a[i] * w.z;
                acc[i][3] += a[i] * w.w;
            }
        }
        __syncthreads();
    }
    // all GEMM reads of hc in this block are complete (syncthreads above)
#pragma unroll
    for (int i = 0; i < 8; i++) {
        int r = r0 + ty * 8 + i;
        if (r < M) {
#pragma unroll
            for (int j = 0; j < 4; j++) {
                int c = tx * 4 + j;
                float z = acc[i][j] + gb[c];
                float gt = 1.f / (1.f + expf(-z));
                float vc = hc[r * DH + c];
                float vn = hn[r * DH + c];
                hc[r * DH + c] = gt * vn + (1.f - gt) * vc;
            }
        }
    }
}

// ---------------- reductions -----------------------------------------------
__device__ __forceinline__ float block_reduce_128(float v, float* sm) {
    for (int o = 16; o > 0; o >>= 1) v += __shfl_xor_sync(0xffffffff, v, o);
    int w = threadIdx.x >> 5;
    if ((threadIdx.x & 31) == 0) sm[w] = v;
    __syncthreads();
    float r = sm[0] + sm[1] + sm[2] + sm[3];
    __syncthreads();
    return r;
}

// per-node gather + bias + LayerNorm (one block of 128 threads per node)
__global__ void k_agg_ln(const float* __restrict__ g, const float* __restrict__ b,
                         const float* __restrict__ lg, const float* __restrict__ lb,
                         float* __restrict__ out) {
    __shared__ float sm[4];
    int n = blockIdx.x;
    int j = threadIdx.x;
    int beg = d_off[n], end = d_off[n + 1];
    float s = 0.f;
    for (int e = beg; e < end; e++) {
        int src = d_csr_src[e];
        s += g[src * DH + j];
    }
    s = s * d_dis[n] + b[j];
    float tot = block_reduce_128(s, sm);
    float mu = tot * (1.f / 128.f);
    float dx = s - mu;
    float var = block_reduce_128(dx * dx, sm) * (1.f / 128.f);
    out[n * DH + j] = dx * rsqrtf(var + LNEPS) * lg[j] + lb[j];
}

// row LayerNorm (warp per row). MODE 1: + relu + *g_epi
template <int MODE>
__global__ void k_ln_rows(const float* __restrict__ in, const float* __restrict__ lg,
                          const float* __restrict__ lb, float* __restrict__ out, int M) {
    int warp = threadIdx.x >> 5, lane = threadIdx.x & 31;
    int r = blockIdx.x * 4 + warp;
    if (r >= M) return;
    float4 v = *(const float4*)&in[r * DH + lane * 4];
    float s = v.x + v.y + v.z + v.w;
    for (int o = 16; o > 0; o >>= 1) s += __shfl_xor_sync(0xffffffff, s, o);
    float mu = s * (1.f / 128.f);
    float dx = v.x - mu, dy = v.y - mu, dz = v.z - mu, dw = v.w - mu;
    float q = dx * dx + dy * dy + dz * dz + dw * dw;
    for (int o = 16; o > 0; o >>= 1) q += __shfl_xor_sync(0xffffffff, q, o);
    float rs = rsqrtf(q * (1.f / 128.f) + LNEPS);
    float4 o4;
    float e = g_epi;
    int c = lane * 4;
    o4.x = dx * rs * lg[c + 0] + lb[c + 0];
    o4.y = dy * rs * lg[c + 1] + lb[c + 1];
    o4.z = dz * rs * lg[c + 2] + lb[c + 2];
    o4.w = dw * rs * lg[c + 3] + lb[c + 3];
    if (MODE == 1) {
        o4.x = fmaxf(o4.x, 0.f) * e;
        o4.y = fmaxf(o4.y, 0.f) * e;
        o4.z = fmaxf(o4.z, 0.f) * e;
        o4.w = fmaxf(o4.w, 0.f) * e;
    }
    *(float4*)&out[r * DH + lane * 4] = o4;
}

// ---------------- RK4 helpers ---------------------------------------------
__global__ void k_rk_pre(float* __restrict__ y, float* __restrict__ acc,
                         const float* __restrict__ h, const float* __restrict__ k,
                         float ycoef, float acoef, int first) {
    int i = blockIdx.x * blockDim.x + threadIdx.x;
    if (i < NN * DH) {
        float kv = k[i];
        y[i] = h[i] + ycoef * g_dt * kv;
        acc[i] = first ? kv : acc[i] + acoef * kv;
    }
}

__global__ void k_rk_final(float* __restrict__ h, const float* __restrict__ acc,
                           const float* __restrict__ k) {
    int i = blockIdx.x * blockDim.x + threadIdx.x;
    if (i < NN * DH) h[i] += (g_dt * (1.f / 6.f)) * (acc[i] + k[i]);
}

__global__ void k_tanh_res(float* __restrict__ kout, const float* __restrict__ hc,
                           const float* __restrict__ y, const float* __restrict__ res_w) {
    int i = blockIdx.x * blockDim.x + threadIdx.x;
    if (i < NN * DH) kout[i] = tanhf(hc[i]) + res_w[0] * y[i];
}

// ---------------- output ---------------------------------------------------
__global__ void k_zero_out(float* out) {
    if (threadIdx.x < DH) out[threadIdx.x] = 0.f;
}

__global__ void k_colmean(const float* __restrict__ a, float* __restrict__ out) {
    int j = threadIdx.x;
    int r0 = blockIdx.x * 128;
    int r1 = min(NN, r0 + 128);
    float s = 0.f;
    for (int r = r0; r < r1; r++) s += a[r * DH + j];
    atomicAdd(&out[j], s * (1.f / (float)NN));
}

// ---------------- host orchestration ---------------------------------------
extern "C" void kernel_launch(void* const* d_in, const int* in_sizes, int n_in,
                              void* d_out, int out_size) {
    const float* x        = (const float*)d_in[0];
    const int*   ei       = (const int*)  d_in[1];
    const float* Wi       = (const float*)d_in[2];
    const float* bi       = (const float*)d_in[3];
    const float* ln_in_g  = (const float*)d_in[4];
    const float* ln_in_b  = (const float*)d_in[5];
    const float* meth     = (const float*)d_in[6];
    const float* hist     = (const float*)d_in[7];
    const float* gcn_w    = (const float*)d_in[8];
    const float* gcn_b    = (const float*)d_in[9];
    const float* ln_g     = (const float*)d_in[10];
    const float* ln_b     = (const float*)d_in[11];
    const float* gate_w   = (const float*)d_in[12];
    const float* gate_b   = (const float*)d_in[13];
    const float* res_w    = (const float*)d_in[14];
    const float* log_depth= (const float*)d_in[15];
    const float* Wo       = (const float*)d_in[16];
    const float* bo       = (const float*)d_in[17];
    const float* ln_out_g = (const float*)d_in[18];
    const float* ln_out_b = (const float*)d_in[19];
    float* out = (float*)d_out;

    float *p_g, *p_A, *p_B, *p_y, *p_k, *p_acc, *p_h;
    cudaGetSymbolAddress((void**)&p_g,   d_g);
    cudaGetSymbolAddress((void**)&p_A,   d_bufA);
    cudaGetSymbolAddress((void**)&p_B,   d_bufB);
    cudaGetSymbolAddress((void**)&p_y,   d_y);
    cudaGetSymbolAddress((void**)&p_k,   d_k);
    cudaGetSymbolAddress((void**)&p_acc, d_acc);
    cudaGetSymbolAddress((void**)&p_h,   d_h);

    const int GEMM_GRID = (NN + 63) / 64;       // 313
    const int EW_GRID   = (NN * DH + 255) / 256; // 10000
    const int LN_GRID   = (NN + 3) / 4;          // 5000

    // graph preprocessing (CSR by target) + scalars
    k_zero_counts<<<(NN + 255) / 256, 256>>>();
    k_count<<<(NE + 255) / 256, 256>>>(ei);
    k_scan<<<1, 1024>>>();
    k_dis<<<(NN + 255) / 256, 256>>>();
    k_fill<<<(NE + 255) / 256, 256>>>(ei);
    k_dt<<<1, 1>>>(log_depth);
    k_epi<<<1, 128>>>(meth, hist);

    // input projection + LN + relu + epigenetic scale
    k_gemm<DIN, 0><<<GEMM_GRID, 256>>>(x, Wi, bi, p_g, NN);
    k_ln_rows<1><<<LN_GRID, 128>>>(p_g, ln_in_g, ln_in_b, p_h, NN);

    // f(in) -> out_k
    auto f_eval = [&](const float* in, float* out_k) {
        // layer 0
        k_gemm<DH, 1><<<GEMM_GRID, 256>>>(in, gcn_w, nullptr, p_g, NN);
        k_agg_ln<<<NN, 128>>>(p_g, gcn_b, ln_g, ln_b, p_A);
        // layer 1 + gate
        k_gemm<DH, 1><<<GEMM_GRID, 256>>>(p_A, gcn_w + DH * DH, nullptr, p_g, NN);
        k_agg_ln<<<NN, 128>>>(p_g, gcn_b + DH, ln_g + DH, ln_b + DH, p_B);
        k_gate<<<GEMM_GRID, 256>>>(p_A, p_B, gate_w, gate_b, NN);
        // layer 2 + gate
        k_gemm<DH, 1><<<GEMM_GRID, 256>>>(p_A, gcn_w + 2 * DH * DH, nullptr, p_g, NN);
        k_agg_ln<<<NN, 128>>>(p_g, gcn_b + 2 * DH, ln_g + 2 * DH, ln_b + 2 * DH, p_B);
        k_gate<<<GEMM_GRID, 256>>>(p_A, p_B, gate_w, gate_b, NN);
        // tanh + residual
        k_tanh_res<<<EW_GRID, 256>>>(out_k, p_A, in, res_w);
    };

    for (int step = 0; step < NT - 1; step++) {
        f_eval(p_h, p_k);                                            // k1
        k_rk_pre<<<EW_GRID, 256>>>(p_y, p_acc, p_h, p_k, 0.5f, 1.f, 1);
        f_eval(p_y, p_k);                                            // k2
        k_rk_pre<<<EW_GRID, 256>>>(p_y, p_acc, p_h, p_k, 0.5f, 2.f, 0);
        f_eval(p_y, p_k);                                            // k3
        k_rk_pre<<<EW_GRID, 256>>>(p_y, p_acc, p_h, p_k, 1.0f, 2.f, 0);
        f_eval(p_y, p_k);                                            // k4
        k_rk_final<<<EW_GRID, 256>>>(p_h, p_acc, p_k);
    }

    // output projection + LN + global mean pool
    k_gemm<DH, 0><<<GEMM_GRID, 256>>>(p_h, Wo, bo, p_g, NN);
    k_ln_rows<0><<<LN_GRID, 128>>>(p_g, ln_out_g, ln_out_b, p_B, NN);
    k_zero_out<<<1, 128>>>(out);
    k_colmean<<<(NN + 127) / 128, 128>>>(p_B, out);
}

// round 3
// speedup vs baseline: 1.1691x; 1.1691x over previous
#include <cuda_runtime.h>
#include <math.h>
#include <stdint.h>

#define NN 20000
#define NE 320000
#define DH 128
#define DIN 64
#define NT 20
#define LNEPS 1e-5f

// ---------------- scratch (device globals: no allocation allowed) ----------
__device__ float g_dt;
__device__ float g_epi;

__device__ float d_g   [NN * DH];
__device__ float d_bufA[NN * DH];
__device__ float d_bufB[NN * DH];
__device__ float d_y   [NN * DH];
__device__ float d_k   [NN * DH];
__device__ float d_acc [NN * DH];
__device__ float d_h   [NN * DH];

__device__ float d_dis[NN];
__device__ int   d_counts[NN];
__device__ int   d_off[NN + 1];
__device__ int   d_cursor[NN];
__device__ int   d_csr_src[NE];

// ---------------- graph preprocessing --------------------------------------
__global__ void k_zero_counts() {
    int i = blockIdx.x * blockDim.x + threadIdx.x;
    if (i < NN) d_counts[i] = 0;
}

__global__ void k_count(const int* __restrict__ ei) {
    int e = blockIdx.x * blockDim.x + threadIdx.x;
    if (e < NE) atomicAdd(&d_counts[ei[NE + e]], 1);
}

// single-block exclusive scan of counts -> off, cursor
__global__ void k_scan() {
    __shared__ int sm[1024];
    int t = threadIdx.x;
    const int CH = (NN + 1023) / 1024;  // 20
    int beg = t * CH;
    int end = min(NN, beg + CH);
    int s = 0;
    for (int i = beg; i < end; i++) s += d_counts[i];
    sm[t] = s;
    __syncthreads();
    for (int o = 1; o < 1024; o <<= 1) {
        int v = (t >= o) ? sm[t - o] : 0;
        __syncthreads();
        sm[t] += v;
        __syncthreads();
    }
    int run = sm[t] - s;  // exclusive prefix
    for (int i = beg; i < end; i++) {
        d_off[i] = run;
        d_cursor[i] = run;
        run += d_counts[i];
    }
    if (t == 1023) d_off[NN] = sm[1023];
}

__global__ void k_dis() {
    int i = blockIdx.x * blockDim.x + threadIdx.x;
    if (i < NN) d_dis[i] = (d_counts[i] > 0) ? rsqrtf((float)d_counts[i]) : 0.f;
}

__global__ void k_fill(const int* __restrict__ ei) {
    int e = blockIdx.x * blockDim.x + threadIdx.x;
    if (e < NE) {
        int c = ei[NE + e];
        int p = atomicAdd(&d_cursor[c], 1);
        d_csr_src[p] = ei[e];
    }
}

// ---------------- scalars --------------------------------------------------
__global__ void k_dt(const float* __restrict__ log_depth) {
    float d = expf(log_depth[0]);
    d = fminf(fmaxf(d, 0.1f), 3.0f);
    g_dt = d / (float)(NT - 1);
}

__global__ void k_epi(const float* __restrict__ meth, const float* __restrict__ hist) {
    __shared__ float sm[4];
    int t = threadIdx.x;  // 128 threads
    float v = 1.f / (1.f + expf(-meth[t]));
    for (int o = 16; o > 0; o >>= 1) v += __shfl_xor_sync(0xffffffff, v, o);
    if ((t & 31) == 0) sm[t >> 5] = v;
    __syncthreads();
    if (t == 0) {
        float tot = sm[0] + sm[1] + sm[2] + sm[3];
        float ms = tot / 128.f;
        float h0 = 1.f / (1.f + expf(-hist[0]));
        float h1 = 1.f / (1.f + expf(-hist[1]));
        float h2 = 1.f / (1.f + expf(-hist[2]));
        float h3 = 1.f / (1.f + expf(-hist[3]));
        float act = 0.5f * (h0 + h2);
        float rep = 0.5f * (h1 + h3);
        float acc = fminf(fmaxf(act - rep + 0.5f, 0.f), 1.f);
        g_epi = acc * (1.f - ms);
    }
}

// ---------------- 3xTF32 tensor-core GEMM building blocks ------------------
__device__ __forceinline__ uint32_t f2tf32(float f) {
    uint32_t r;
    asm("cvt.rna.tf32.f32 %0, %1;" : "=r"(r) : "f"(f));
    return r;
}

// v -> (hi, lo) with hi = tf32(v), lo = tf32(v - hi)
__device__ __forceinline__ void split_tf32(float v, uint32_t& hi, uint32_t& lo) {
    hi = f2tf32(v);
    lo = f2tf32(v - __uint_as_float(hi));
}

__device__ __forceinline__ void mma_tf32(float c[4], const uint32_t a[4], const uint32_t b[2]) {
    asm volatile(
        "mma.sync.aligned.m16n8k8.row.col.f32.tf32.tf32.f32 "
        "{%0,%1,%2,%3},{%4,%5,%6,%7},{%8,%9},{%0,%1,%2,%3};"
        : "+f"(c[0]), "+f"(c[1]), "+f"(c[2]), "+f"(c[3])
        : "r"(a[0]), "r"(a[1]), "r"(a[2]), "r"(a[3]), "r"(b[0]), "r"(b[1]));
}

#define SA_STRIDE 36
#define SW_STRIDE 132

// C[M x 128] = A[M x K] @ W[K x 128], 3xTF32 compensated.
// EPI 0: C = acc + bias[col]    EPI 1: C = acc * dis[row]
// Block: 64 rows x 128 cols, 256 threads (8 warps: 2 m x 4 n), warp tile 32x32.
template <int K, int EPI>
__global__ void k_gemm_tc(const float* __restrict__ A, const float* __restrict__ W,
                          const float* __restrict__ bias, float* __restrict__ C, int M) {
    __shared__ uint32_t sA[2][64 * SA_STRIDE];   // [hi/lo]
    __shared__ uint32_t sW[2][32 * SW_STRIDE];
    int tid = threadIdx.x;
    int warp = tid >> 5, lane = tid & 31;
    int grp = lane >> 2, qid = lane & 3;
    int wm = warp >> 2, wn = warp & 3;
    int r0 = blockIdx.x * 64;

    float acc[2][4][4];
#pragma unroll
    for (int mi = 0; mi < 2; mi++)
#pragma unroll
        for (int ni = 0; ni < 4; ni++)
#pragma unroll
            for (int j = 0; j < 4; j++) acc[mi][ni][j] = 0.f;

    for (int k0 = 0; k0 < K; k0 += 32) {
#pragma unroll
        for (int it = 0; it < 2; it++) {
            int i = tid + it * 256;
            int row = i >> 3, q = i & 7;
            int gr = r0 + row;
            float4 v = make_float4(0.f, 0.f, 0.f, 0.f);
            if (gr < M) v = *(const float4*)&A[gr * K + k0 + q * 4];
            uint4 uh, ul;
            split_tf32(v.x, uh.x, ul.x); split_tf32(v.y, uh.y, ul.y);
            split_tf32(v.z, uh.z, ul.z); split_tf32(v.w, uh.w, ul.w);
            *(uint4*)&sA[0][row * SA_STRIDE + q * 4] = uh;
            *(uint4*)&sA[1][row * SA_STRIDE + q * 4] = ul;
        }
#pragma unroll
        for (int it = 0; it < 4; it++) {
            int i = tid + it * 256;
            int kr = i >> 5, cq = i & 31;
            float4 v = *(const float4*)&W[(k0 + kr) * DH + cq * 4];
            uint4 uh, ul;
            split_tf32(v.x, uh.x, ul.x); split_tf32(v.y, uh.y, ul.y);
            split_tf32(v.z, uh.z, ul.z); split_tf32(v.w, uh.w, ul.w);
            *(uint4*)&sW[0][kr * SW_STRIDE + cq * 4] = uh;
            *(uint4*)&sW[1][kr * SW_STRIDE + cq * 4] = ul;
        }
        __syncthreads();
#pragma unroll
        for (int kk = 0; kk < 32; kk += 8) {
            uint32_t ah[2][4], al[2][4], bh[4][2], bl[4][2];
#pragma unroll
            for (int mi = 0; mi < 2; mi++) {
                int r = wm * 32 + mi * 16 + grp;
                int i0 = r * SA_STRIDE + kk + qid;
                int i1 = (r + 8) * SA_STRIDE + kk + qid;
                ah[mi][0] = sA[0][i0];     ah[mi][1] = sA[0][i1];
                ah[mi][2] = sA[0][i0 + 4]; ah[mi][3] = sA[0][i1 + 4];
                al[mi][0] = sA[1][i0];     al[mi][1] = sA[1][i1];
                al[mi][2] = sA[1][i0 + 4]; al[mi][3] = sA[1][i1 + 4];
            }
#pragma unroll
            for (int ni = 0; ni < 4; ni++) {
                int n = wn * 32 + ni * 8 + grp;
                bh[ni][0] = sW[0][(kk + qid) * SW_STRIDE + n];
                bh[ni][1] = sW[0][(kk + qid + 4) * SW_STRIDE + n];
                bl[ni][0] = sW[1][(kk + qid) * SW_STRIDE + n];
                bl[ni][1] = sW[1][(kk + qid + 4) * SW_STRIDE + n];
            }
#pragma unroll
            for (int mi = 0; mi < 2; mi++)
#pragma unroll
                for (int ni = 0; ni < 4; ni++) {
                    mma_tf32(acc[mi][ni], al[mi], bh[ni]);
                    mma_tf32(acc[mi][ni], ah[mi], bl[ni]);
                    mma_tf32(acc[mi][ni], ah[mi], bh[ni]);
                }
        }
        __syncthreads();
    }

#pragma unroll
    for (int mi = 0; mi < 2; mi++) {
        int row = r0 + wm * 32 + mi * 16 + grp;
#pragma unroll
        for (int half = 0; half < 2; half++) {
            int r = row + half * 8;
            if (r < M) {
                float sc = (EPI == 1) ? d_dis[r] : 0.f;
#pragma unroll
                for (int ni = 0; ni < 4; ni++) {
                    int col = wn * 32 + ni * 8 + 2 * qid;
                    float v0 = acc[mi][ni][half * 2 + 0];
                    float v1 = acc[mi][ni][half * 2 + 1];
                    if (EPI == 0) { v0 += bias[col]; v1 += bias[col + 1]; }
                    else          { v0 *= sc;        v1 *= sc; }
                    C[r * DH + col] = v0;
                    C[r * DH + col + 1] = v1;
                }
            }
        }
    }
}

// gate GEMM (K=256, A = concat(hc, hn)), 3xTF32 compensated.
// FUSE 0: hc = g*hn + (1-g)*hc
// FUSE 1: kout = tanh(g*hn + (1-g)*hc) + res_w * y   (hc not written)
template <int FUSE>
__global__ void k_gate_tc(float* __restrict__ hc, const float* __restrict__ hn,
                          const float* __restrict__ GW, const float* __restrict__ gb, int M,
                          float* __restrict__ kout, const float* __restrict__ y,
                          const float* __restrict__ res_w) {
    __shared__ uint32_t sA[2][64 * SA_STRIDE];
    __shared__ uint32_t sW[2][32 * SW_STRIDE];
    int tid = threadIdx.x;
    int warp = tid >> 5, lane = tid & 31;
    int grp = lane >> 2, qid = lane & 3;
    int wm = warp >> 2, wn = warp & 3;
    int r0 = blockIdx.x * 64;

    float acc[2][4][4];
#pragma unroll
    for (int mi = 0; mi < 2; mi++)
#pragma unroll
        for (int ni = 0; ni < 4; ni++)
#pragma unroll
            for (int j = 0; j < 4; j++) acc[mi][ni][j] = 0.f;

    for (int k0 = 0; k0 < 256; k0 += 32) {
#pragma unroll
        for (int it = 0; it < 2; it++) {
            int i = tid + it * 256;
            int row = i >> 3, q = i & 7;
            int gr = r0 + row;
            int c = k0 + q * 4;
            float4 v = make_float4(0.f, 0.f, 0.f, 0.f);
            if (gr < M)
                v = (c < DH) ? *(const float4*)&hc[gr * DH + c]
                             : *(const float4*)&hn[gr * DH + (c - DH)];
            uint4 uh, ul;
            split_tf32(v.x, uh.x, ul.x); split_tf32(v.y, uh.y, ul.y);
            split_tf32(v.z, uh.z, ul.z); split_tf32(v.w, uh.w, ul.w);
            *(uint4*)&sA[0][row * SA_STRIDE + q * 4] = uh;
            *(uint4*)&sA[1][row * SA_STRIDE + q * 4] = ul;
        }
#pragma unroll
        for (int it = 0; it < 4; it++) {
            int i = tid + it * 256;
            int kr = i >> 5, cq = i & 31;
            float4 v = *(const float4*)&GW[(k0 + kr) * DH + cq * 4];
            uint4 uh, ul;
            split_tf32(v.x, uh.x, ul.x); split_tf32(v.y, uh.y, ul.y);
            split_tf32(v.z, uh.z, ul.z); split_tf32(v.w, uh.w, ul.w);
            *(uint4*)&sW[0][kr * SW_STRIDE + cq * 4] = uh;
            *(uint4*)&sW[1][kr * SW_STRIDE + cq * 4] = ul;
        }
        __syncthreads();
#pragma unroll
        for (int kk = 0; kk < 32; kk += 8) {
            uint32_t ah[2][4], al[2][4], bh[4][2], bl[4][2];
#pragma unroll
            for (int mi = 0; mi < 2; mi++) {
                int r = wm * 32 + mi * 16 + grp;
                int i0 = r * SA_STRIDE + kk + qid;
                int i1 = (r + 8) * SA_STRIDE + kk + qid;
                ah[mi][0] = sA[0][i0];     ah[mi][1] = sA[0][i1];
                ah[mi][2] = sA[0][i0 + 4]; ah[mi][3] = sA[0][i1 + 4];
                al[mi][0] = sA[1][i0];     al[mi][1] = sA[1][i1];
                al[mi][2] = sA[1][i0 + 4]; al[mi][3] = sA[1][i1 + 4];
            }
#pragma unroll
            for (int ni = 0; ni < 4; ni++) {
                int n = wn * 32 + ni * 8 + grp;
                bh[ni][0] = sW[0][(kk + qid) * SW_STRIDE + n];
                bh[ni][1] = sW[0][(kk + qid + 4) * SW_STRIDE + n];
                bl[ni][0] = sW[1][(kk + qid) * SW_STRIDE + n];
                bl[ni][1] = sW[1][(kk + qid + 4) * SW_STRIDE + n];
            }
#pragma unroll
            for (int mi = 0; mi < 2; mi++)
#pragma unroll
                for (int ni = 0; ni < 4; ni++) {
                    mma_tf32(acc[mi][ni], al[mi], bh[ni]);
                    mma_tf32(acc[mi][ni], ah[mi], bl[ni]);
                    mma_tf32(acc[mi][ni], ah[mi], bh[ni]);
                }
        }
        __syncthreads();
    }
    // all block-wide reads of hc complete (last __syncthreads above);
    // this block only writes its own rows.
    float rw = FUSE ? res_w[0] : 0.f;
#pragma unroll
    for (int mi = 0; mi < 2; mi++) {
        int row = r0 + wm * 32 + mi * 16 + grp;
#pragma unroll
        for (int half = 0; half < 2; half++) {
            int r = row + half * 8;
            if (r < M) {
#pragma unroll
                for (int ni = 0; ni < 4; ni++) {
                    int col = wn * 32 + ni * 8 + 2 * qid;
#pragma unroll
                    for (int j = 0; j < 2; j++) {
                        int c = col + j;
                        float z = acc[mi][ni][half * 2 + j] + gb[c];
                        float gt = 1.f / (1.f + expf(-z));
                        int idx = r * DH + c;
                        float blend = gt * hn[idx] + (1.f - gt) * hc[idx];
                        if (FUSE) kout[idx] = tanhf(blend) + rw * y[idx];
                        else      hc[idx] = blend;
                    }
                }
            }
        }
    }
}

// ---------------- reductions -----------------------------------------------
__device__ __forceinline__ float block_reduce_128(float v, float* sm) {
    for (int o = 16; o > 0; o >>= 1) v += __shfl_xor_sync(0xffffffff, v, o);
    int w = threadIdx.x >> 5;
    if ((threadIdx.x & 31) == 0) sm[w] = v;
    __syncthreads();
    float r = sm[0] + sm[1] + sm[2] + sm[3];
    __syncthreads();
    return r;
}

// per-node gather + bias + LayerNorm (one block of 128 threads per node)
__global__ void k_agg_ln(const float* __restrict__ g, const float* __restrict__ b,
                         const float* __restrict__ lg, const float* __restrict__ lb,
                         float* __restrict__ out) {
    __shared__ float sm[4];
    int n = blockIdx.x;
    int j = threadIdx.x;
    int beg = d_off[n], end = d_off[n + 1];
    float s = 0.f;
    for (int e = beg; e < end; e++) {
        int src = d_csr_src[e];
        s += g[src * DH + j];
    }
    s = s * d_dis[n] + b[j];
    float tot = block_reduce_128(s, sm);
    float mu = tot * (1.f / 128.f);
    float dx = s - mu;
    float var = block_reduce_128(dx * dx, sm) * (1.f / 128.f);
    out[n * DH + j] = dx * rsqrtf(var + LNEPS) * lg[j] + lb[j];
}

// row LayerNorm (warp per row). MODE 1: + relu + *g_epi
template <int MODE>
__global__ void k_ln_rows(const float* __restrict__ in, const float* __restrict__ lg,
                          const float* __restrict__ lb, float* __restrict__ out, int M) {
    int warp = threadIdx.x >> 5, lane = threadIdx.x & 31;
    int r = blockIdx.x * 4 + warp;
    if (r >= M) return;
    float4 v = *(const float4*)&in[r * DH + lane * 4];
    float s = v.x + v.y + v.z + v.w;
    for (int o = 16; o > 0; o >>= 1) s += __shfl_xor_sync(0xffffffff, s, o);
    float mu = s * (1.f / 128.f);
    float dx = v.x - mu, dy = v.y - mu, dz = v.z - mu, dw = v.w - mu;
    float q = dx * dx + dy * dy + dz * dz + dw * dw;
    for (int o = 16; o > 0; o >>= 1) q += __shfl_xor_sync(0xffffffff, q, o);
    float rs = rsqrtf(q * (1.f / 128.f) + LNEPS);
    float4 o4;
    float e = g_epi;
    int c = lane * 4;
    o4.x = dx * rs * lg[c + 0] + lb[c + 0];
    o4.y = dy * rs * lg[c + 1] + lb[c + 1];
    o4.z = dz * rs * lg[c + 2] + lb[c + 2];
    o4.w = dw * rs * lg[c + 3] + lb[c + 3];
    if (MODE == 1) {
        o4.x = fmaxf(o4.x, 0.f) * e;
        o4.y = fmaxf(o4.y, 0.f) * e;
        o4.z = fmaxf(o4.z, 0.f) * e;
        o4.w = fmaxf(o4.w, 0.f) * e;
    }
    *(float4*)&out[r * DH + lane * 4] = o4;
}

// ---------------- RK4 helpers ---------------------------------------------
__global__ void k_rk_pre(float* __restrict__ y, float* __restrict__ acc,
                         const float* __restrict__ h, const float* __restrict__ k,
                         float ycoef, float acoef, int first) {
    int i = blockIdx.x * blockDim.x + threadIdx.x;
    if (i < NN * DH) {
        float kv = k[i];
        y[i] = h[i] + ycoef * g_dt * kv;
        acc[i] = first ? kv : acc[i] + acoef * kv;
    }
}

__global__ void k_rk_final(float* __restrict__ h, const float* __restrict__ acc,
                           const float* __restrict__ k) {
    int i = blockIdx.x * blockDim.x + threadIdx.x;
    if (i < NN * DH) h[i] += (g_dt * (1.f / 6.f)) * (acc[i] + k[i]);
}

// ---------------- output ---------------------------------------------------
__global__ void k_zero_out(float* out) {
    if (threadIdx.x < DH) out[threadIdx.x] = 0.f;
}

__global__ void k_colmean(const float* __restrict__ a, float* __restrict__ out) {
    int j = threadIdx.x;
    int r0 = blockIdx.x * 128;
    int r1 = min(NN, r0 + 128);
    float s = 0.f;
    for (int r = r0; r < r1; r++) s += a[r * DH + j];
    atomicAdd(&out[j], s * (1.f / (float)NN));
}

// ---------------- host orchestration ---------------------------------------
extern "C" void kernel_launch(void* const* d_in, const int* in_sizes, int n_in,
                              void* d_out, int out_size) {
    const float* x        = (const float*)d_in[0];
    const int*   ei       = (const int*)  d_in[1];
    const float* Wi       = (const float*)d_in[2];
    const float* bi       = (const float*)d_in[3];
    const float* ln_in_g  = (const float*)d_in[4];
    const float* ln_in_b  = (const float*)d_in[5];
    const float* meth     = (const float*)d_in[6];
    const float* hist     = (const float*)d_in[7];
    const float* gcn_w    = (const float*)d_in[8];
    const float* gcn_b    = (const float*)d_in[9];
    const float* ln_g     = (const float*)d_in[10];
    const float* ln_b     = (const float*)d_in[11];
    const float* gate_w   = (const float*)d_in[12];
    const float* gate_b   = (const float*)d_in[13];
    const float* res_w    = (const float*)d_in[14];
    const float* log_depth= (const float*)d_in[15];
    const float* Wo       = (const float*)d_in[16];
    const float* bo       = (const float*)d_in[17];
    const float* ln_out_g = (const float*)d_in[18];
    const float* ln_out_b = (const float*)d_in[19];
    float* out = (float*)d_out;

    float *p_g, *p_A, *p_B, *p_y, *p_k, *p_acc, *p_h;
    cudaGetSymbolAddress((void**)&p_g,   d_g);
    cudaGetSymbolAddress((void**)&p_A,   d_bufA);
    cudaGetSymbolAddress((void**)&p_B,   d_bufB);
    cudaGetSymbolAddress((void**)&p_y,   d_y);
    cudaGetSymbolAddress((void**)&p_k,   d_k);
    cudaGetSymbolAddress((void**)&p_acc, d_acc);
    cudaGetSymbolAddress((void**)&p_h,   d_h);

    const int GEMM_GRID = (NN + 63) / 64;        // 313
    const int EW_GRID   = (NN * DH + 255) / 256; // 10000
    const int LN_GRID   = (NN + 3) / 4;          // 5000

    // graph preprocessing (CSR by target) + scalars
    k_zero_counts<<<(NN + 255) / 256, 256>>>();
    k_count<<<(NE + 255) / 256, 256>>>(ei);
    k_scan<<<1, 1024>>>();
    k_dis<<<(NN + 255) / 256, 256>>>();
    k_fill<<<(NE + 255) / 256, 256>>>(ei);
    k_dt<<<1, 1>>>(log_depth);
    k_epi<<<1, 128>>>(meth, hist);

    // input projection + LN + relu + epigenetic scale
    k_gemm_tc<DIN, 0><<<GEMM_GRID, 256>>>(x, Wi, bi, p_g, NN);
    k_ln_rows<1><<<LN_GRID, 128>>>(p_g, ln_in_g, ln_in_b, p_h, NN);

    // f(in) -> out_k
    auto f_eval = [&](const float* in, float* out_k) {
        // layer 0
        k_gemm_tc<DH, 1><<<GEMM_GRID, 256>>>(in, gcn_w, nullptr, p_g, NN);
        k_agg_ln<<<NN, 128>>>(p_g, gcn_b, ln_g, ln_b, p_A);
        // layer 1 + gate
        k_gemm_tc<DH, 1><<<GEMM_GRID, 256>>>(p_A, gcn_w + DH * DH, nullptr, p_g, NN);
        k_agg_ln<<<NN, 128>>>(p_g, gcn_b + DH, ln_g + DH, ln_b + DH, p_B);
        k_gate_tc<0><<<GEMM_GRID, 256>>>(p_A, p_B, gate_w, gate_b, NN,
                                         nullptr, nullptr, nullptr);
        // layer 2 + gate fused with tanh + residual
        k_gemm_tc<DH, 1><<<GEMM_GRID, 256>>>(p_A, gcn_w + 2 * DH * DH, nullptr, p_g, NN);
        k_agg_ln<<<NN, 128>>>(p_g, gcn_b + 2 * DH, ln_g + 2 * DH, ln_b + 2 * DH, p_B);
        k_gate_tc<1><<<GEMM_GRID, 256>>>(p_A, p_B, gate_w, gate_b, NN,
                                         out_k, in, res_w);
    };

    for (int step = 0; step < NT - 1; step++) {
        f_eval(p_h, p_k);                                            // k1
        k_rk_pre<<<EW_GRID, 256>>>(p_y, p_acc, p_h, p_k, 0.5f, 1.f, 1);
        f_eval(p_y, p_k);                                            // k2
        k_rk_pre<<<EW_GRID, 256>>>(p_y, p_acc, p_h, p_k, 0.5f, 2.f, 0);
        f_eval(p_y, p_k);                                            // k3
        k_rk_pre<<<EW_GRID, 256>>>(p_y, p_acc, p_h, p_k, 1.0f, 2.f, 0);
        f_eval(p_y, p_k);                                            // k4
        k_rk_final<<<EW_GRID, 256>>>(p_h, p_acc, p_k);
    }

    // output projection + LN + global mean pool
    k_gemm_tc<DH, 0><<<GEMM_GRID, 256>>>(p_h, Wo, bo, p_g, NN);
    k_ln_rows<0><<<LN_GRID, 128>>>(p_g, ln_out_g, ln_out_b, p_B, NN);
    k_zero_out<<<1, 128>>>(out);
    k_colmean<<<(NN + 127) / 128, 128>>>(p_B, out);
}

// round 4
// speedup vs baseline: 1.2531x; 1.0719x over previous
#include <cuda_runtime.h>
#include <math.h>
#include <stdint.h>

#define NN 20000
#define NE 320000
#define DH 128
#define DIN 64
#define NT 20
#define LNEPS 1e-5f

// ---------------- scratch (device globals: no allocation allowed) ----------
__device__ float g_dt;
__device__ float g_epi;

__device__ float d_g   [NN * DH];
__device__ float d_bufA[NN * DH];
__device__ float d_bufB[NN * DH];
__device__ float d_y   [NN * DH];
__device__ float d_acc [NN * DH];
__device__ float d_h   [NN * DH];

__device__ float d_dis[NN];
__device__ int   d_counts[NN];
__device__ int   d_off[NN + 1];
__device__ int   d_cursor[NN];
__device__ int   d_csr_src[NE];

// pre-split tf32 weights (hi/lo). layout offsets:
//   Wi: 0..8192, gcn: 8192..57344 (3x16384), gate: 57344..90112, Wo: 90112..106496
#define WOFF_I    0
#define WOFF_GCN  8192
#define WOFF_GATE 57344
#define WOFF_WO   90112
#define WTOT      106496
__device__ uint32_t d_whi[WTOT];
__device__ uint32_t d_wlo[WTOT];

// ---------------- tf32 helpers ---------------------------------------------
__device__ __forceinline__ uint32_t f2tf32(float f) {
    uint32_t r;
    asm("cvt.rna.tf32.f32 %0, %1;" : "=r"(r) : "f"(f));
    return r;
}
__device__ __forceinline__ void split_tf32(float v, uint32_t& hi, uint32_t& lo) {
    hi = f2tf32(v);
    lo = f2tf32(v - __uint_as_float(hi));
}
__device__ __forceinline__ void mma_tf32(float c[4], const uint32_t a[4], const uint32_t b[2]) {
    asm volatile(
        "mma.sync.aligned.m16n8k8.row.col.f32.tf32.tf32.f32 "
        "{%0,%1,%2,%3},{%4,%5,%6,%7},{%8,%9},{%0,%1,%2,%3};"
        : "+f"(c[0]), "+f"(c[1]), "+f"(c[2]), "+f"(c[3])
        : "r"(a[0]), "r"(a[1]), "r"(a[2]), "r"(a[3]), "r"(b[0]), "r"(b[1]));
}

// ---------------- prologue kernels -----------------------------------------
// launch 0: zero counts + scalars (dt, epi)
__global__ void k_pre0(const float* __restrict__ log_depth,
                       const float* __restrict__ meth,
                       const float* __restrict__ hist) {
    int i = blockIdx.x * blockDim.x + threadIdx.x;
    if (i < NN) d_counts[i] = 0;
    if (blockIdx.x == 0 && threadIdx.x < 32) {
        int t = threadIdx.x;
        float v = 0.f;
        for (int j = t; j < 128; j += 32) v += 1.f / (1.f + expf(-meth[j]));
        for (int o = 16; o > 0; o >>= 1) v += __shfl_xor_sync(0xffffffff, v, o);
        if (t == 0) {
            float ms = v / 128.f;
            float h0 = 1.f / (1.f + expf(-hist[0]));
            float h1 = 1.f / (1.f + expf(-hist[1]));
            float h2 = 1.f / (1.f + expf(-hist[2]));
            float h3 = 1.f / (1.f + expf(-hist[3]));
            float act = 0.5f * (h0 + h2);
            float rep = 0.5f * (h1 + h3);
            float acc = fminf(fmaxf(act - rep + 0.5f, 0.f), 1.f);
            g_epi = acc * (1.f - ms);
            float d = expf(log_depth[0]);
            d = fminf(fmaxf(d, 0.1f), 3.0f);
            g_dt = d / (float)(NT - 1);
        }
    }
}

__global__ void k_count(const int* __restrict__ ei) {
    int e = blockIdx.x * blockDim.x + threadIdx.x;
    if (e < NE) atomicAdd(&d_counts[ei[NE + e]], 1);
}

// single-block exclusive scan of counts -> off, cursor; also dis
__global__ void k_scan() {
    __shared__ int sm[1024];
    int t = threadIdx.x;
    const int CH = (NN + 1023) / 1024;  // 20
    int beg = t * CH;
    int end = min(NN, beg + CH);
    int s = 0;
    for (int i = beg; i < end; i++) s += d_counts[i];
    sm[t] = s;
    __syncthreads();
    for (int o = 1; o < 1024; o <<= 1) {
        int v = (t >= o) ? sm[t - o] : 0;
        __syncthreads();
        sm[t] += v;
        __syncthreads();
    }
    int run = sm[t] - s;  // exclusive prefix
    for (int i = beg; i < end; i++) {
        int c = d_counts[i];
        d_off[i] = run;
        d_cursor[i] = run;
        d_dis[i] = (c > 0) ? rsqrtf((float)c) : 0.f;
        run += c;
    }
    if (t == 1023) d_off[NN] = sm[1023];
}

__global__ void k_fill(const int* __restrict__ ei) {
    int e = blockIdx.x * blockDim.x + threadIdx.x;
    if (e < NE) {
        int c = ei[NE + e];
        int p = atomicAdd(&d_cursor[c], 1);
        d_csr_src[p] = ei[e];
    }
}

// split all weights into tf32 hi/lo once
__global__ void k_split_w(const float* __restrict__ Wi, const float* __restrict__ gcn,
                          const float* __restrict__ gate, const float* __restrict__ Wo) {
    int i = blockIdx.x * blockDim.x + threadIdx.x;
    if (i >= WTOT) return;
    float v;
    if (i < WOFF_GCN)       v = Wi[i - WOFF_I];
    else if (i < WOFF_GATE) v = gcn[i - WOFF_GCN];
    else if (i < WOFF_WO)   v = gate[i - WOFF_GATE];
    else                    v = Wo[i - WOFF_WO];
    uint32_t hi, lo;
    split_tf32(v, hi, lo);
    d_whi[i] = hi;
    d_wlo[i] = lo;
}

#define SA_STRIDE 36
#define SW_STRIDE 132

// C[M x 128] = A[M x K] @ W[K x 128], 3xTF32 compensated, pre-split W.
// EPI 0: C = acc + bias[col]    EPI 1: C = acc * dis[row]
template <int K, int EPI>
__global__ void k_gemm_tc(const float* __restrict__ A,
                          const uint32_t* __restrict__ whi, const uint32_t* __restrict__ wlo,
                          const float* __restrict__ bias, float* __restrict__ C, int M) {
    __shared__ uint32_t sA[2][64 * SA_STRIDE];   // [hi/lo]
    __shared__ uint32_t sW[2][32 * SW_STRIDE];
    int tid = threadIdx.x;
    int warp = tid >> 5, lane = tid & 31;
    int grp = lane >> 2, qid = lane & 3;
    int wm = warp >> 2, wn = warp & 3;
    int r0 = blockIdx.x * 64;

    float acc[2][4][4];
#pragma unroll
    for (int mi = 0; mi < 2; mi++)
#pragma unroll
        for (int ni = 0; ni < 4; ni++)
#pragma unroll
            for (int j = 0; j < 4; j++) acc[mi][ni][j] = 0.f;

    for (int k0 = 0; k0 < K; k0 += 32) {
#pragma unroll
        for (int it = 0; it < 2; it++) {
            int i = tid + it * 256;
            int row = i >> 3, q = i & 7;
            int gr = r0 + row;
            float4 v = make_float4(0.f, 0.f, 0.f, 0.f);
            if (gr < M) v = *(const float4*)&A[gr * K + k0 + q * 4];
            uint4 uh, ul;
            split_tf32(v.x, uh.x, ul.x); split_tf32(v.y, uh.y, ul.y);
            split_tf32(v.z, uh.z, ul.z); split_tf32(v.w, uh.w, ul.w);
            *(uint4*)&sA[0][row * SA_STRIDE + q * 4] = uh;
            *(uint4*)&sA[1][row * SA_STRIDE + q * 4] = ul;
        }
#pragma unroll
        for (int it = 0; it < 4; it++) {
            int i = tid + it * 256;
            int kr = i >> 5, cq = i & 31;
            int gi = (k0 + kr) * DH + cq * 4;
            *(uint4*)&sW[0][kr * SW_STRIDE + cq * 4] = *(const uint4*)&whi[gi];
            *(uint4*)&sW[1][kr * SW_STRIDE + cq * 4] = *(const uint4*)&wlo[gi];
        }
        __syncthreads();
#pragma unroll
        for (int kk = 0; kk < 32; kk += 8) {
            uint32_t ah[2][4], al[2][4], bh[4][2], bl[4][2];
#pragma unroll
            for (int mi = 0; mi < 2; mi++) {
                int r = wm * 32 + mi * 16 + grp;
                int i0 = r * SA_STRIDE + kk + qid;
                int i1 = (r + 8) * SA_STRIDE + kk + qid;
                ah[mi][0] = sA[0][i0];     ah[mi][1] = sA[0][i1];
                ah[mi][2] = sA[0][i0 + 4]; ah[mi][3] = sA[0][i1 + 4];
                al[mi][0] = sA[1][i0];     al[mi][1] = sA[1][i1];
                al[mi][2] = sA[1][i0 + 4]; al[mi][3] = sA[1][i1 + 4];
            }
#pragma unroll
            for (int ni = 0; ni < 4; ni++) {
                int n = wn * 32 + ni * 8 + grp;
                bh[ni][0] = sW[0][(kk + qid) * SW_STRIDE + n];
                bh[ni][1] = sW[0][(kk + qid + 4) * SW_STRIDE + n];
                bl[ni][0] = sW[1][(kk + qid) * SW_STRIDE + n];
                bl[ni][1] = sW[1][(kk + qid + 4) * SW_STRIDE + n];
            }
#pragma unroll
            for (int mi = 0; mi < 2; mi++)
#pragma unroll
                for (int ni = 0; ni < 4; ni++) {
                    mma_tf32(acc[mi][ni], al[mi], bh[ni]);
                    mma_tf32(acc[mi][ni], ah[mi], bl[ni]);
                    mma_tf32(acc[mi][ni], ah[mi], bh[ni]);
                }
        }
        __syncthreads();
    }

#pragma unroll
    for (int mi = 0; mi < 2; mi++) {
        int row = r0 + wm * 32 + mi * 16 + grp;
#pragma unroll
        for (int half = 0; half < 2; half++) {
            int r = row + half * 8;
            if (r < M) {
                float sc = (EPI == 1) ? d_dis[r] : 0.f;
#pragma unroll
                for (int ni = 0; ni < 4; ni++) {
                    int col = wn * 32 + ni * 8 + 2 * qid;
                    float v0 = acc[mi][ni][half * 2 + 0];
                    float v1 = acc[mi][ni][half * 2 + 1];
                    if (EPI == 0) { v0 += bias[col]; v1 += bias[col + 1]; }
                    else          { v0 *= sc;        v1 *= sc; }
                    C[r * DH + col] = v0;
                    C[r * DH + col + 1] = v1;
                }
            }
        }
    }
}

// gate GEMM (K=256, A = concat(hc, hn)), 3xTF32 compensated, pre-split W.
// FUSE 0: hc = g*hn + (1-g)*hc
// FUSE 1: kv = tanh(blend) + rw*yin;  yout = h + ycoef*dt*kv;
//         acc = first ? kv : acc + acoef*kv
// FUSE 2: kv = tanh(blend) + rw*yin;  h += dt/6*(acc + kv)
template <int FUSE>
__global__ void k_gate_tc(float* __restrict__ hc, const float* __restrict__ hn,
                          const uint32_t* __restrict__ whi, const uint32_t* __restrict__ wlo,
                          const float* __restrict__ gb, int M,
                          const float* yin, float* yout,
                          float* h, float* acc_buf,
                          const float* __restrict__ res_w,
                          float ycoef, float acoef, int first) {
    __shared__ uint32_t sA[2][64 * SA_STRIDE];
    __shared__ uint32_t sW[2][32 * SW_STRIDE];
    int tid = threadIdx.x;
    int warp = tid >> 5, lane = tid & 31;
    int grp = lane >> 2, qid = lane & 3;
    int wm = warp >> 2, wn = warp & 3;
    int r0 = blockIdx.x * 64;

    float acc[2][4][4];
#pragma unroll
    for (int mi = 0; mi < 2; mi++)
#pragma unroll
        for (int ni = 0; ni < 4; ni++)
#pragma unroll
            for (int j = 0; j < 4; j++) acc[mi][ni][j] = 0.f;

    for (int k0 = 0; k0 < 256; k0 += 32) {
#pragma unroll
        for (int it = 0; it < 2; it++) {
            int i = tid + it * 256;
            int row = i >> 3, q = i & 7;
            int gr = r0 + row;
            int c = k0 + q * 4;
            float4 v = make_float4(0.f, 0.f, 0.f, 0.f);
            if (gr < M)
                v = (c < DH) ? *(const float4*)&hc[gr * DH + c]
                             : *(const float4*)&hn[gr * DH + (c - DH)];
            uint4 uh, ul;
            split_tf32(v.x, uh.x, ul.x); split_tf32(v.y, uh.y, ul.y);
            split_tf32(v.z, uh.z, ul.z); split_tf32(v.w, uh.w, ul.w);
            *(uint4*)&sA[0][row * SA_STRIDE + q * 4] = uh;
            *(uint4*)&sA[1][row * SA_STRIDE + q * 4] = ul;
        }
#pragma unroll
        for (int it = 0; it < 4; it++) {
            int i = tid + it * 256;
            int kr = i >> 5, cq = i & 31;
            int gi = (k0 + kr) * DH + cq * 4;
            *(uint4*)&sW[0][kr * SW_STRIDE + cq * 4] = *(const uint4*)&whi[gi];
            *(uint4*)&sW[1][kr * SW_STRIDE + cq * 4] = *(const uint4*)&wlo[gi];
        }
        __syncthreads();
#pragma unroll
        for (int kk = 0; kk < 32; kk += 8) {
            uint32_t ah[2][4], al[2][4], bh[4][2], bl[4][2];
#pragma unroll
            for (int mi = 0; mi < 2; mi++) {
                int r = wm * 32 + mi * 16 + grp;
                int i0 = r * SA_STRIDE + kk + qid;
                int i1 = (r + 8) * SA_STRIDE + kk + qid;
                ah[mi][0] = sA[0][i0];     ah[mi][1] = sA[0][i1];
                ah[mi][2] = sA[0][i0 + 4]; ah[mi][3] = sA[0][i1 + 4];
                al[mi][0] = sA[1][i0];     al[mi][1] = sA[1][i1];
                al[mi][2] = sA[1][i0 + 4]; al[mi][3] = sA[1][i1 + 4];
            }
#pragma unroll
            for (int ni = 0; ni < 4; ni++) {
                int n = wn * 32 + ni * 8 + grp;
                bh[ni][0] = sW[0][(kk + qid) * SW_STRIDE + n];
                bh[ni][1] = sW[0][(kk + qid + 4) * SW_STRIDE + n];
                bl[ni][0] = sW[1][(kk + qid) * SW_STRIDE + n];
                bl[ni][1] = sW[1][(kk + qid + 4) * SW_STRIDE + n];
            }
#pragma unroll
            for (int mi = 0; mi < 2; mi++)
#pragma unroll
                for (int ni = 0; ni < 4; ni++) {
                    mma_tf32(acc[mi][ni], al[mi], bh[ni]);
                    mma_tf32(acc[mi][ni], ah[mi], bl[ni]);
                    mma_tf32(acc[mi][ni], ah[mi], bh[ni]);
                }
        }
        __syncthreads();
    }
    // all block-wide reads of hc complete (last __syncthreads above);
    // this block only writes its own rows.
    float rw = (FUSE != 0) ? res_w[0] : 0.f;
    float dt = (FUSE != 0) ? g_dt : 0.f;
#pragma unroll
    for (int mi = 0; mi < 2; mi++) {
        int row = r0 + wm * 32 + mi * 16 + grp;
#pragma unroll
        for (int half = 0; half < 2; half++) {
            int r = row + half * 8;
            if (r < M) {
#pragma unroll
                for (int ni = 0; ni < 4; ni++) {
                    int col = wn * 32 + ni * 8 + 2 * qid;
#pragma unroll
                    for (int j = 0; j < 2; j++) {
                        int c = col + j;
                        float z = acc[mi][ni][half * 2 + j] + gb[c];
                        float gt = 1.f / (1.f + expf(-z));
                        int idx = r * DH + c;
                        float blend = gt * hn[idx] + (1.f - gt) * hc[idx];
                        if (FUSE == 0) {
                            hc[idx] = blend;
                        } else if (FUSE == 1) {
                            float kv = tanhf(blend) + rw * yin[idx];
                            float yv = h[idx] + ycoef * dt * kv;
                            float av = first ? kv : acc_buf[idx] + acoef * kv;
                            yout[idx] = yv;
                            acc_buf[idx] = av;
                        } else {
                            float kv = tanhf(blend) + rw * yin[idx];
                            h[idx] += (dt * (1.f / 6.f)) * (acc_buf[idx] + kv);
                        }
                    }
                }
            }
        }
    }
}

// ---------------- aggregation + LayerNorm (warp per node) ------------------
__global__ void k_agg_ln(const float* __restrict__ g, const float* __restrict__ b,
                         const float* __restrict__ lg, const float* __restrict__ lb,
                         float* __restrict__ out) {
    int warp = threadIdx.x >> 5, lane = threadIdx.x & 31;
    int n = blockIdx.x * 8 + warp;
    if (n >= NN) return;
    int beg = d_off[n], end = d_off[n + 1];
    int c4 = lane * 4;
    float4 a0 = make_float4(0.f, 0.f, 0.f, 0.f);
    float4 a1 = make_float4(0.f, 0.f, 0.f, 0.f);
    int e = beg;
    for (; e + 1 < end; e += 2) {
        int s0 = d_csr_src[e];
        int s1 = d_csr_src[e + 1];
        float4 v0 = *(const float4*)&g[s0 * DH + c4];
        float4 v1 = *(const float4*)&g[s1 * DH + c4];
        a0.x += v0.x; a0.y += v0.y; a0.z += v0.z; a0.w += v0.w;
        a1.x += v1.x; a1.y += v1.y; a1.z += v1.z; a1.w += v1.w;
    }
    if (e < end) {
        int s0 = d_csr_src[e];
        float4 v0 = *(const float4*)&g[s0 * DH + c4];
        a0.x += v0.x; a0.y += v0.y; a0.z += v0.z; a0.w += v0.w;
    }
    float dis = d_dis[n];
    float4 b4 = *(const float4*)&b[c4];
    float sx = (a0.x + a1.x) * dis + b4.x;
    float sy = (a0.y + a1.y) * dis + b4.y;
    float sz = (a0.z + a1.z) * dis + b4.z;
    float sw = (a0.w + a1.w) * dis + b4.w;
    float s = sx + sy + sz + sw;
    for (int o = 16; o > 0; o >>= 1) s += __shfl_xor_sync(0xffffffff, s, o);
    float mu = s * (1.f / 128.f);
    float dx = sx - mu, dy = sy - mu, dz = sz - mu, dw = sw - mu;
    float q = dx * dx + dy * dy + dz * dz + dw * dw;
    for (int o = 16; o > 0; o >>= 1) q += __shfl_xor_sync(0xffffffff, q, o);
    float rs = rsqrtf(q * (1.f / 128.f) + LNEPS);
    float4 lg4 = *(const float4*)&lg[c4];
    float4 lb4 = *(const float4*)&lb[c4];
    float4 o4;
    o4.x = dx * rs * lg4.x + lb4.x;
    o4.y = dy * rs * lg4.y + lb4.y;
    o4.z = dz * rs * lg4.z + lb4.z;
    o4.w = dw * rs * lg4.w + lb4.w;
    *(float4*)&out[n * DH + c4] = o4;
}

// row LayerNorm (warp per row). MODE 1: + relu + *g_epi
template <int MODE>
__global__ void k_ln_rows(const float* __restrict__ in, const float* __restrict__ lg,
                          const float* __restrict__ lb, float* __restrict__ out, int M) {
    int warp = threadIdx.x >> 5, lane = threadIdx.x & 31;
    int r = blockIdx.x * 4 + warp;
    if (r >= M) return;
    float4 v = *(const float4*)&in[r * DH + lane * 4];
    float s = v.x + v.y + v.z + v.w;
    for (int o = 16; o > 0; o >>= 1) s += __shfl_xor_sync(0xffffffff, s, o);
    float mu = s * (1.f / 128.f);
    float dx = v.x - mu, dy = v.y - mu, dz = v.z - mu, dw = v.w - mu;
    float q = dx * dx + dy * dy + dz * dz + dw * dw;
    for (int o = 16; o > 0; o >>= 1) q += __shfl_xor_sync(0xffffffff, q, o);
    float rs = rsqrtf(q * (1.f / 128.f) + LNEPS);
    float4 o4;
    float e = g_epi;
    int c = lane * 4;
    o4.x = dx * rs * lg[c + 0] + lb[c + 0];
    o4.y = dy * rs * lg[c + 1] + lb[c + 1];
    o4.z = dz * rs * lg[c + 2] + lb[c + 2];
    o4.w = dw * rs * lg[c + 3] + lb[c + 3];
    if (MODE == 1) {
        o4.x = fmaxf(o4.x, 0.f) * e;
        o4.y = fmaxf(o4.y, 0.f) * e;
        o4.z = fmaxf(o4.z, 0.f) * e;
        o4.w = fmaxf(o4.w, 0.f) * e;
    }
    *(float4*)&out[r * DH + lane * 4] = o4;
}

// ---------------- output ---------------------------------------------------
__global__ void k_zero_out(float* out) {
    if (threadIdx.x < DH) out[threadIdx.x] = 0.f;
}

__global__ void k_colmean(const float* __restrict__ a, float* __restrict__ out) {
    int j = threadIdx.x;
    int r0 = blockIdx.x * 128;
    int r1 = min(NN, r0 + 128);
    float s = 0.f;
    for (int r = r0; r < r1; r++) s += a[r * DH + j];
    atomicAdd(&out[j], s * (1.f / (float)NN));
}

// ---------------- host orchestration ---------------------------------------
extern "C" void kernel_launch(void* const* d_in, const int* in_sizes, int n_in,
                              void* d_out, int out_size) {
    const float* x        = (const float*)d_in[0];
    const int*   ei       = (const int*)  d_in[1];
    const float* Wi       = (const float*)d_in[2];
    const float* bi       = (const float*)d_in[3];
    const float* ln_in_g  = (const float*)d_in[4];
    const float* ln_in_b  = (const float*)d_in[5];
    const float* meth     = (const float*)d_in[6];
    const float* hist     = (const float*)d_in[7];
    const float* gcn_w    = (const float*)d_in[8];
    const float* gcn_b    = (const float*)d_in[9];
    const float* ln_g     = (const float*)d_in[10];
    const float* ln_b     = (const float*)d_in[11];
    const float* gate_w   = (const float*)d_in[12];
    const float* gate_b   = (const float*)d_in[13];
    const float* res_w    = (const float*)d_in[14];
    const float* log_depth= (const float*)d_in[15];
    const float* Wo       = (const float*)d_in[16];
    const float* bo       = (const float*)d_in[17];
    const float* ln_out_g = (const float*)d_in[18];
    const float* ln_out_b = (const float*)d_in[19];
    float* out = (float*)d_out;

    float *p_g, *p_A, *p_B, *p_y, *p_acc, *p_h;
    uint32_t *p_whi, *p_wlo;
    cudaGetSymbolAddress((void**)&p_g,   d_g);
    cudaGetSymbolAddress((void**)&p_A,   d_bufA);
    cudaGetSymbolAddress((void**)&p_B,   d_bufB);
    cudaGetSymbolAddress((void**)&p_y,   d_y);
    cudaGetSymbolAddress((void**)&p_acc, d_acc);
    cudaGetSymbolAddress((void**)&p_h,   d_h);
    cudaGetSymbolAddress((void**)&p_whi, d_whi);
    cudaGetSymbolAddress((void**)&p_wlo, d_wlo);

    const int GEMM_GRID = (NN + 63) / 64;   // 313
    const int AGG_GRID  = (NN + 7) / 8;     // 2500
    const int LN_GRID   = (NN + 3) / 4;     // 5000

    // prologue (5 launches) -> launch #5 is the first GEMM (ncu capture target)
    k_pre0<<<(NN + 255) / 256, 256>>>(log_depth, meth, hist);
    k_count<<<(NE + 255) / 256, 256>>>(ei);
    k_scan<<<1, 1024>>>();
    k_fill<<<(NE + 255) / 256, 256>>>(ei);
    k_split_w<<<(WTOT + 255) / 256, 256>>>(Wi, gcn_w, gate_w, Wo);

    // input projection + LN + relu + epigenetic scale
    k_gemm_tc<DIN, 0><<<GEMM_GRID, 256>>>(x, p_whi + WOFF_I, p_wlo + WOFF_I, bi, p_g, NN);
    k_ln_rows<1><<<LN_GRID, 128>>>(p_g, ln_in_g, ln_in_b, p_h, NN);

    // f(in) with fused RK epilogue in the second gate
    // mode 1: y = h + ycoef*dt*k; acc = first ? k : acc + acoef*k
    // mode 2: h += dt/6*(acc + k)
    auto f_eval = [&](const float* in, int mode, float ycoef, float acoef, int first) {
        const uint32_t* g0h = p_whi + WOFF_GCN;
        const uint32_t* g0l = p_wlo + WOFF_GCN;
        // layer 0
        k_gemm_tc<DH, 1><<<GEMM_GRID, 256>>>(in, g0h, g0l, nullptr, p_g, NN);
        k_agg_ln<<<AGG_GRID, 256>>>(p_g, gcn_b, ln_g, ln_b, p_A);
        // layer 1 + plain gate
        k_gemm_tc<DH, 1><<<GEMM_GRID, 256>>>(p_A, g0h + DH * DH, g0l + DH * DH, nullptr, p_g, NN);
        k_agg_ln<<<AGG_GRID, 256>>>(p_g, gcn_b + DH, ln_g + DH, ln_b + DH, p_B);
        k_gate_tc<0><<<GEMM_GRID, 256>>>(p_A, p_B, p_whi + WOFF_GATE, p_wlo + WOFF_GATE,
                                         gate_b, NN, nullptr, nullptr, nullptr, nullptr,
                                         nullptr, 0.f, 0.f, 0);
        // layer 2 + gate fused with tanh/residual + RK update
        k_gemm_tc<DH, 1><<<GEMM_GRID, 256>>>(p_A, g0h + 2 * DH * DH, g0l + 2 * DH * DH,
                                             nullptr, p_g, NN);
        k_agg_ln<<<AGG_GRID, 256>>>(p_g, gcn_b + 2 * DH, ln_g + 2 * DH, ln_b + 2 * DH, p_B);
        if (mode == 1)
            k_gate_tc<1><<<GEMM_GRID, 256>>>(p_A, p_B, p_whi + WOFF_GATE, p_wlo + WOFF_GATE,
                                             gate_b, NN, in, p_y, p_h, p_acc,
                                             res_w, ycoef, acoef, first);
        else
            k_gate_tc<2><<<GEMM_GRID, 256>>>(p_A, p_B, p_whi + WOFF_GATE, p_wlo + WOFF_GATE,
                                             gate_b, NN, in, nullptr, p_h, p_acc,
                                             res_w, 0.f, 0.f, 0);
    };

    for (int step = 0; step < NT - 1; step++) {
        f_eval(p_h, 1, 0.5f, 1.f, 1);   // k1: y = h + dt/2*k1, acc = k1
        f_eval(p_y, 1, 0.5f, 2.f, 0);   // k2: y = h + dt/2*k2, acc += 2k2
        f_eval(p_y, 1, 1.0f, 2.f, 0);   // k3: y = h + dt*k3,   acc += 2k3
        f_eval(p_y, 2, 0.f, 0.f, 0);    // k4: h += dt/6*(acc + k4)
    }

    // output projection + LN + global mean pool
    k_gemm_tc<DH, 0><<<GEMM_GRID, 256>>>(p_h, p_whi + WOFF_WO, p_wlo + WOFF_WO, bo, p_g, NN);
    k_ln_rows<0><<<LN_GRID, 128>>>(p_g, ln_out_g, ln_out_b, p_B, NN);
    k_zero_out<<<1, 128>>>(out);
    k_colmean<<<(NN + 127) / 128, 128>>>(p_B, out);
}